// round 7
// baseline (speedup 1.0000x reference)
#include <cuda_runtime.h>

// Shapes: B=4, LQ=128, LF=64, NW=2, NFR=8, E=128, D=128, V=64, G=NW*NFR=16
// Outputs concatenated (fp32):
//   frag_code     [4,2,8,128]   ->  [0,     8192)
//   query_code    [4,2,8,128]   ->  [8192,  16384)
//   frag_self_att [4,2,8,64]    ->  [16384, 20480)
//   qf_gate       [4,16,128]    ->  [20480, 28672)
//   query (proj)  [4,128,128]   ->  [28672, 94208)

#define OC_FRAG 0
#define OC_QC   8192
#define OC_FSA  16384
#define OC_GATE 20480
#define OC_Q    28672
#define OUT_TOTAL 94208

// -------- scratch (no cudaMalloc allowed) --------
__device__ float g_fragp[4096 * 128];   // projected fragment, rows (b,g,l)
__device__ float g_qatt [512 * 64];     // q_att  [b*128+q][v]
__device__ float g_fatt [4096 * 64];    // f_att  [(bg*64+l)][v]
__device__ float g_qf   [64 * 128 * 64];// qf after max+q_att  [(bg*128+q)][v]
__device__ float g_qp   [512 * 128];    // fallback home for projected query
__device__ float g_dump [OUT_TOTAL];    // fallback output sink

// -------- packed fp32x2 helpers --------
__device__ __forceinline__ unsigned long long dup_f32(float x) {
    unsigned long long d; unsigned u = __float_as_uint(x);
    asm("mov.b64 %0, {%1, %1};" : "=l"(d) : "r"(u));
    return d;
}
__device__ __forceinline__ void fma2(unsigned long long &d,
                                     unsigned long long a,
                                     unsigned long long b) {
    asm("fma.rn.f32x2 %0, %1, %2, %0;" : "+l"(d) : "l"(a), "l"(b));
}
__device__ __forceinline__ void unpack2(unsigned long long v, float &lo, float &hi) {
    unsigned a, b;
    asm("mov.b64 {%0, %1}, %2;" : "=r"(a), "=r"(b) : "l"(v));
    lo = __uint_as_float(a); hi = __uint_as_float(b);
}

// ============================================================
// K1: projection  y = x @ W + b   for query (512 rows) and fragment (4096 rows)
// grid 72 CTAs x 64 rows, 256 thr, dyn smem 98304 B
// ============================================================
__global__ void __launch_bounds__(256) proj_kernel(
    const float* __restrict__ query, const float* __restrict__ fragment,
    const float* __restrict__ W, const float* __restrict__ bias,
    float* __restrict__ out_q)
{
    extern __shared__ float sm[];
    float* Xs  = sm;          // 64*128
    float* Wsm = sm + 8192;   // 128*128
    int r0 = blockIdx.x * 64;
    const float* src; float* dst;
    if (r0 < 512) { src = query + r0 * 128;           dst = out_q   + r0 * 128; }
    else          { src = fragment + (r0 - 512) * 128; dst = g_fragp + (r0 - 512) * 128; }
    int tid = threadIdx.x;
    const float4* s4 = (const float4*)src;
    float4* Xs4 = (float4*)Xs;
#pragma unroll
    for (int it = 0; it < 8; ++it) Xs4[tid + it * 256] = s4[tid + it * 256];
    const float4* W4 = (const float4*)W;
    float4* Wsm4 = (float4*)Wsm;
#pragma unroll
    for (int it = 0; it < 16; ++it) Wsm4[tid + it * 256] = W4[tid + it * 256];
    __syncthreads();
    int tx = tid & 15, ty = tid >> 4;
    float acc[4][8];
#pragma unroll
    for (int i = 0; i < 4; ++i)
#pragma unroll
        for (int j = 0; j < 8; ++j) acc[i][j] = 0.f;
#pragma unroll 4
    for (int k = 0; k < 128; ++k) {
        float a0 = Xs[(ty*4+0)*128+k], a1 = Xs[(ty*4+1)*128+k];
        float a2 = Xs[(ty*4+2)*128+k], a3 = Xs[(ty*4+3)*128+k];
        float4 w0 = Wsm4[(k*128 + tx*8) >> 2];
        float4 w1 = Wsm4[((k*128 + tx*8) >> 2) + 1];
        float wb[8] = {w0.x,w0.y,w0.z,w0.w,w1.x,w1.y,w1.z,w1.w};
#pragma unroll
        for (int j = 0; j < 8; ++j) {
            acc[0][j] += a0*wb[j]; acc[1][j] += a1*wb[j];
            acc[2][j] += a2*wb[j]; acc[3][j] += a3*wb[j];
        }
    }
#pragma unroll
    for (int i = 0; i < 4; ++i) {
        int r = ty*4 + i;
#pragma unroll
        for (int j = 0; j < 8; ++j)
            dst[r*128 + tx*8 + j] = acc[i][j] + bias[tx*8 + j];
    }
}

// ============================================================
// K2: fragment self-attention softmax + frag_code
// grid 64 CTAs = (b,w,f), 128 thr
// ============================================================
__global__ void __launch_bounds__(128) selfatt_kernel(
    const float* __restrict__ selfW, const float* __restrict__ fmask,
    float* __restrict__ o_fsa, float* __restrict__ o_frag)
{
    __shared__ float es[64];
    __shared__ float att[64];
    __shared__ float ssum;
    int cta = blockIdx.x;              // ((b*2+w)*8+f)
    int w = (cta >> 3) & 1;
    int tid = threadIdx.x;
    if (tid < 64) {
        const float* row = g_fragp + (cta*64 + tid) * 128;
        const float* sw = selfW + w * 128;
        float d = 0.f;
#pragma unroll 4
        for (int k = 0; k < 128; ++k) d += row[k] * sw[k];
        es[tid] = expf(d) * fmask[cta*64 + tid];
    }
    __syncthreads();
    if (tid == 0) {
        float s = 0.f;
        for (int l = 0; l < 64; ++l) s += es[l];
        ssum = s + 1e-7f;
    }
    __syncthreads();
    if (tid < 64) {
        float a = es[tid] / ssum;
        att[tid] = a;
        o_fsa[cta*64 + tid] = a;
    }
    __syncthreads();
    float acc = 0.f;
#pragma unroll 4
    for (int l = 0; l < 64; ++l) acc += g_fragp[(cta*64 + l)*128 + tid] * att[l];
    o_frag[cta*128 + tid] = acc;
}

// ============================================================
// K3: q_att = Qp @ q_att_W ; f_att = fragp @ f_att_W
// grid 72 CTAs x 64 rows, 256 thr, dyn smem 65536 B
// ============================================================
__global__ void __launch_bounds__(256) attproj_kernel(
    const float* __restrict__ qp, const float* __restrict__ qW,
    const float* __restrict__ fW)
{
    extern __shared__ float sm[];
    float* Xs  = sm;          // 64*128
    float* Wsm = sm + 8192;   // 128*64
    int r0 = blockIdx.x * 64;
    const float* src; const float* Wg; float* dst;
    if (r0 < 512) { src = qp + r0*128;               Wg = qW; dst = g_qatt + r0*64; }
    else          { src = g_fragp + (r0 - 512)*128;  Wg = fW; dst = g_fatt + (r0 - 512)*64; }
    int tid = threadIdx.x;
    const float4* s4 = (const float4*)src;
    float4* Xs4 = (float4*)Xs;
#pragma unroll
    for (int it = 0; it < 8; ++it) Xs4[tid + it*256] = s4[tid + it*256];
    const float4* W4 = (const float4*)Wg;
    float4* Wsm4 = (float4*)Wsm;
#pragma unroll
    for (int it = 0; it < 8; ++it) Wsm4[tid + it*256] = W4[tid + it*256];
    __syncthreads();
    int tx = tid & 15, ty = tid >> 4;
    float acc[4][4];
#pragma unroll
    for (int i = 0; i < 4; ++i)
#pragma unroll
        for (int j = 0; j < 4; ++j) acc[i][j] = 0.f;
#pragma unroll 4
    for (int k = 0; k < 128; ++k) {
        float a0 = Xs[(ty*4+0)*128+k], a1 = Xs[(ty*4+1)*128+k];
        float a2 = Xs[(ty*4+2)*128+k], a3 = Xs[(ty*4+3)*128+k];
        float4 wv = Wsm4[k*16 + tx];
        float wb[4] = {wv.x, wv.y, wv.z, wv.w};
#pragma unroll
        for (int j = 0; j < 4; ++j) {
            acc[0][j] += a0*wb[j]; acc[1][j] += a1*wb[j];
            acc[2][j] += a2*wb[j]; acc[3][j] += a3*wb[j];
        }
    }
#pragma unroll
    for (int i = 0; i < 4; ++i) {
        int r = ty*4 + i;
#pragma unroll
        for (int j = 0; j < 4; ++j) dst[r*64 + tx*4 + j] = acc[i][j];
    }
}

// ============================================================
// K4: the big one.
// qf[q,v] = q_att[q,v] + max_l ( f_att[l,v] + sum_d Q[q,d]*s_l[d]*W[d,v] )
// grid 128 CTAs = (b,g) x q-half(64), 256 thr, dyn smem 101120 B
// Inner GEMM uses packed fma.rn.f32x2 (2 fp32 FMA / inst), acc packed along q.
// ============================================================
__global__ void __launch_bounds__(256) big_kernel(
    const float* __restrict__ qp, const float* __restrict__ qfW)
{
    extern __shared__ float sm[];
    float* Qt   = sm;            // [128][68]  k-major Q chunk (padded, 16B aligned rows)
    float* Wsm  = sm + 8704;     // [128][64]  qf_att_W
    float* Ws   = sm + 16896;    // [128][64]  scaled W for current l
    float* s_s  = sm + 25088;    // [128]      frag row (scale vector)
    float* fa_s = sm + 25216;    // [64]       f_att row

    int cta = blockIdx.x;
    int bg = cta >> 1;           // b*16+g
    int qh = cta & 1;
    int b  = bg >> 4;
    int q0 = qh << 6;
    int tid = threadIdx.x;
    int fragbase = bg * 64;

    // stage Q (transposed) and W
    const float* qb = qp + (b*128 + q0) * 128;
#pragma unroll
    for (int it = 0; it < 8; ++it) {
        int idx = tid + it * 256;       // 0..2047
        int q  = idx >> 5;              // 0..63
        int k4 = idx & 31;
        float4 v = *(const float4*)(qb + q*128 + k4*4);
        float* d = Qt + (k4*4)*68 + q;
        d[0] = v.x; d[68] = v.y; d[136] = v.z; d[204] = v.w;
    }
    {
        float4* Wsm4 = (float4*)Wsm;
        const float4* qfW4 = (const float4*)qfW;
#pragma unroll
        for (int it = 0; it < 8; ++it) Wsm4[tid + it*256] = qfW4[tid + it*256];
    }

    int tx = tid & 15, ty = tid >> 4;
    const float* Qtp = Qt + (ty << 2);
    const float* Wsp = Ws + (tx << 2);
    const float4* Wsm4c = (const float4*)Wsm;
    float4* Ws4 = (float4*)Ws;

    unsigned long long acc[2][4];
    float M[4][4];
#pragma unroll
    for (int i = 0; i < 4; ++i)
#pragma unroll
        for (int j = 0; j < 4; ++j) M[i][j] = -3.4e38f;
#pragma unroll
    for (int p = 0; p < 2; ++p)
#pragma unroll
        for (int j = 0; j < 4; ++j) acc[p][j] = 0ULL;

    for (int l = 0; l < 64; ++l) {
        __syncthreads();   // also covers initial Qt/Wsm staging on l==0
        if (tid < 128)      s_s[tid]        = g_fragp[(fragbase + l)*128 + tid];
        else if (tid < 192) fa_s[tid - 128] = g_fatt[(bg*64 + l)*64 + (tid - 128)];
        __syncthreads();
        // Ws[k][v] = s[k] * W[k][v]
#pragma unroll
        for (int it = 0; it < 8; ++it) {
            int idx = tid + it*256;     // float4 index, 0..2047
            float4 wv = Wsm4c[idx];
            float sk = s_s[idx >> 4];
            float4 r; r.x = wv.x*sk; r.y = wv.y*sk; r.z = wv.z*sk; r.w = wv.w*sk;
            Ws4[idx] = r;
        }
        __syncthreads();

#pragma unroll 8
        for (int k = 0; k < 128; ++k) {
            ulonglong2 a = *(const ulonglong2*)(Qtp + k*68);   // (q0,q1),(q2,q3)
            float4 wv = *(const float4*)(Wsp + k*64);
            unsigned long long b0 = dup_f32(wv.x);
            unsigned long long b1 = dup_f32(wv.y);
            unsigned long long b2 = dup_f32(wv.z);
            unsigned long long b3 = dup_f32(wv.w);
            fma2(acc[0][0], a.x, b0); fma2(acc[0][1], a.x, b1);
            fma2(acc[0][2], a.x, b2); fma2(acc[0][3], a.x, b3);
            fma2(acc[1][0], a.y, b0); fma2(acc[1][1], a.y, b1);
            fma2(acc[1][2], a.y, b2); fma2(acc[1][3], a.y, b3);
        }

        float fav[4] = {fa_s[tx*4+0], fa_s[tx*4+1], fa_s[tx*4+2], fa_s[tx*4+3]};
#pragma unroll
        for (int p = 0; p < 2; ++p)
#pragma unroll
            for (int j = 0; j < 4; ++j) {
                float lo, hi;
                unpack2(acc[p][j], lo, hi);
                M[2*p][j]   = fmaxf(M[2*p][j],   lo + fav[j]);
                M[2*p+1][j] = fmaxf(M[2*p+1][j], hi + fav[j]);
                acc[p][j] = 0ULL;
            }
    }

    // epilogue: add q_att (l-independent) and store
#pragma unroll
    for (int i = 0; i < 4; ++i) {
        int q = q0 + ty*4 + i;
#pragma unroll
        for (int j = 0; j < 4; ++j) {
            int v = tx*4 + j;
            g_qf[(bg*128 + q)*64 + v] = M[i][j] + g_qatt[(b*128 + q)*64 + v];
        }
    }
}

// ============================================================
// K5: gate / val softmax over LQ + query_code
// grid 64 CTAs = (b,g), 128 thr
// ============================================================
__global__ void __launch_bounds__(128) final_kernel(
    const float* __restrict__ qp, const float* __restrict__ qmask,
    const float* __restrict__ gate_w, const float* __restrict__ val_w,
    float* __restrict__ o_gate, float* __restrict__ o_qc)
{
    __shared__ float gw[64], vw[64], red[128], norm[128];
    int bg = blockIdx.x;
    int b = bg >> 4;
    int tid = threadIdx.x;
    if (tid < 64) { gw[tid] = gate_w[tid]; vw[tid] = val_w[tid]; }
    __syncthreads();
    const float* row = g_qf + (bg*128 + tid) * 64;
    float dg = 0.f, dv = 0.f;
#pragma unroll 4
    for (int v = 0; v < 64; ++v) { float x = row[v]; dg += x*gw[v]; dv += x*vw[v]; }
    float qm = qmask[b*128 + tid];
    o_gate[bg*128 + tid] = qm / (1.f + expf(-dg));
    float e2 = expf(dv) * qm;
    red[tid] = e2;
    __syncthreads();
    for (int s = 64; s > 0; s >>= 1) {
        if (tid < s) red[tid] += red[tid + s];
        __syncthreads();
    }
    norm[tid] = e2 / (red[0] + 1e-7f);
    __syncthreads();
    const float* qpb = qp + b * 128 * 128;
    float acc = 0.f;
#pragma unroll 4
    for (int q = 0; q < 128; ++q) acc += qpb[q*128 + tid] * norm[q];
    o_qc[bg*128 + tid] = acc;
}

// ============================================================
extern "C" void kernel_launch(void* const* d_in, const int* in_sizes, int n_in,
                              void* d_out, int out_size)
{
    (void)in_sizes; (void)n_in;
    const float* query    = (const float*)d_in[0];
    const float* fragment = (const float*)d_in[1];
    const float* qmask    = (const float*)d_in[2];
    const float* fmask    = (const float*)d_in[3];
    const float* proj_W   = (const float*)d_in[4];
    const float* proj_b   = (const float*)d_in[5];
    const float* selfW    = (const float*)d_in[6];
    const float* qattW    = (const float*)d_in[7];
    const float* fattW    = (const float*)d_in[8];
    const float* qfW      = (const float*)d_in[9];
    const float* gatew    = (const float*)d_in[10];
    const float* valw     = (const float*)d_in[11];
    float* out = (float*)d_out;

    // Output pointers: if out buffer matches the concatenated-tuple layout,
    // write there; otherwise write into a scratch sink (prevents OOB, keeps
    // the launch deterministic and capturable either way).
    float *o_frag, *o_qc, *o_fsa, *o_gate, *o_q;
    if (out_size >= OUT_TOTAL) {
        o_frag = out + OC_FRAG; o_qc = out + OC_QC; o_fsa = out + OC_FSA;
        o_gate = out + OC_GATE; o_q = out + OC_Q;
    } else {
        float* dp = nullptr;
        cudaGetSymbolAddress((void**)&dp, g_dump);
        float* qpd = nullptr;
        cudaGetSymbolAddress((void**)&qpd, g_qp);
        o_frag = dp + OC_FRAG; o_qc = dp + OC_QC; o_fsa = dp + OC_FSA;
        o_gate = dp + OC_GATE; o_q = qpd;
    }

    cudaFuncSetAttribute(proj_kernel,    cudaFuncAttributeMaxDynamicSharedMemorySize, 98304);
    cudaFuncSetAttribute(attproj_kernel, cudaFuncAttributeMaxDynamicSharedMemorySize, 65536);
    cudaFuncSetAttribute(big_kernel,     cudaFuncAttributeMaxDynamicSharedMemorySize, 101120);

    proj_kernel   <<<72, 256, 98304>>>(query, fragment, proj_W, proj_b, o_q);
    selfatt_kernel<<<64, 128>>>(selfW, fmask, o_fsa, o_frag);
    attproj_kernel<<<72, 256, 65536>>>(o_q, qattW, fattW);
    big_kernel    <<<128, 256, 101120>>>(o_q, qfW);
    final_kernel  <<<64, 128>>>(o_q, qmask, gatew, valw, o_gate, o_qc);
}

// round 9
// speedup vs baseline: 1.3897x; 1.3897x over previous
#include <cuda_runtime.h>

// Shapes: B=4, LQ=128, LF=64, NW=2, NFR=8, E=128, D=128, V=64, G=NW*NFR=16
// Outputs concatenated (fp32):
//   frag_code     [4,2,8,128]   ->  [0,     8192)
//   query_code    [4,2,8,128]   ->  [8192,  16384)
//   frag_self_att [4,2,8,64]    ->  [16384, 20480)
//   qf_gate       [4,16,128]    ->  [20480, 28672)
//   query (proj)  [4,128,128]   ->  [28672, 94208)

#define OC_FRAG 0
#define OC_QC   8192
#define OC_FSA  16384
#define OC_GATE 20480
#define OC_Q    28672
#define OUT_TOTAL 94208

// -------- scratch (no cudaMalloc allowed) --------
__device__ float g_fragp[4096 * 128];   // projected fragment, rows (b,g,l)
__device__ float g_qatt [512 * 64];     // q_att  [b*128+q][v]
__device__ float g_fatt [4096 * 64];    // f_att  [(bg*64+l)][v]
__device__ float g_qf   [64 * 128 * 64];// partial max over l in [0,32)
__device__ float g_qf2  [64 * 128 * 64];// partial max over l in [32,64)
__device__ float g_qp   [512 * 128];    // fallback home for projected query
__device__ float g_dump [OUT_TOTAL];    // fallback output sink

// -------- packed fp32x2 helpers --------
__device__ __forceinline__ unsigned long long dup_f32(float x) {
    unsigned long long d; unsigned u = __float_as_uint(x);
    asm("mov.b64 %0, {%1, %1};" : "=l"(d) : "r"(u));
    return d;
}
__device__ __forceinline__ void fma2(unsigned long long &d,
                                     unsigned long long a,
                                     unsigned long long b) {
    asm("fma.rn.f32x2 %0, %1, %2, %0;" : "+l"(d) : "l"(a), "l"(b));
}
__device__ __forceinline__ void unpack2(unsigned long long v, float &lo, float &hi) {
    unsigned a, b;
    asm("mov.b64 {%0, %1}, %2;" : "=r"(a), "=r"(b) : "l"(v));
    lo = __uint_as_float(a); hi = __uint_as_float(b);
}

// ============================================================
// K1: projection  y = x @ W + b   for query (512 rows) and fragment (4096 rows)
// ============================================================
__global__ void __launch_bounds__(256) proj_kernel(
    const float* __restrict__ query, const float* __restrict__ fragment,
    const float* __restrict__ W, const float* __restrict__ bias,
    float* __restrict__ out_q)
{
    extern __shared__ float sm[];
    float* Xs  = sm;          // 64*128
    float* Wsm = sm + 8192;   // 128*128
    int r0 = blockIdx.x * 64;
    const float* src; float* dst;
    if (r0 < 512) { src = query + r0 * 128;           dst = out_q   + r0 * 128; }
    else          { src = fragment + (r0 - 512) * 128; dst = g_fragp + (r0 - 512) * 128; }
    int tid = threadIdx.x;
    const float4* s4 = (const float4*)src;
    float4* Xs4 = (float4*)Xs;
#pragma unroll
    for (int it = 0; it < 8; ++it) Xs4[tid + it * 256] = s4[tid + it * 256];
    const float4* W4 = (const float4*)W;
    float4* Wsm4 = (float4*)Wsm;
#pragma unroll
    for (int it = 0; it < 16; ++it) Wsm4[tid + it * 256] = W4[tid + it * 256];
    __syncthreads();
    int tx = tid & 15, ty = tid >> 4;
    float acc[4][8];
#pragma unroll
    for (int i = 0; i < 4; ++i)
#pragma unroll
        for (int j = 0; j < 8; ++j) acc[i][j] = 0.f;
#pragma unroll 4
    for (int k = 0; k < 128; ++k) {
        float a0 = Xs[(ty*4+0)*128+k], a1 = Xs[(ty*4+1)*128+k];
        float a2 = Xs[(ty*4+2)*128+k], a3 = Xs[(ty*4+3)*128+k];
        float4 w0 = Wsm4[(k*128 + tx*8) >> 2];
        float4 w1 = Wsm4[((k*128 + tx*8) >> 2) + 1];
        float wb[8] = {w0.x,w0.y,w0.z,w0.w,w1.x,w1.y,w1.z,w1.w};
#pragma unroll
        for (int j = 0; j < 8; ++j) {
            acc[0][j] += a0*wb[j]; acc[1][j] += a1*wb[j];
            acc[2][j] += a2*wb[j]; acc[3][j] += a3*wb[j];
        }
    }
#pragma unroll
    for (int i = 0; i < 4; ++i) {
        int r = ty*4 + i;
#pragma unroll
        for (int j = 0; j < 8; ++j)
            dst[r*128 + tx*8 + j] = acc[i][j] + bias[tx*8 + j];
    }
}

// ============================================================
// K2: fragment self-attention softmax + frag_code
// ============================================================
__global__ void __launch_bounds__(128) selfatt_kernel(
    const float* __restrict__ selfW, const float* __restrict__ fmask,
    float* __restrict__ o_fsa, float* __restrict__ o_frag)
{
    __shared__ float es[64];
    __shared__ float att[64];
    __shared__ float ssum;
    int cta = blockIdx.x;              // ((b*2+w)*8+f)
    int w = (cta >> 3) & 1;
    int tid = threadIdx.x;
    if (tid < 64) {
        const float* row = g_fragp + (cta*64 + tid) * 128;
        const float* sw = selfW + w * 128;
        float d = 0.f;
#pragma unroll 4
        for (int k = 0; k < 128; ++k) d += row[k] * sw[k];
        es[tid] = expf(d) * fmask[cta*64 + tid];
    }
    __syncthreads();
    if (tid == 0) {
        float s = 0.f;
        for (int l = 0; l < 64; ++l) s += es[l];
        ssum = s + 1e-7f;
    }
    __syncthreads();
    if (tid < 64) {
        float a = es[tid] / ssum;
        att[tid] = a;
        o_fsa[cta*64 + tid] = a;
    }
    __syncthreads();
    float acc = 0.f;
#pragma unroll 4
    for (int l = 0; l < 64; ++l) acc += g_fragp[(cta*64 + l)*128 + tid] * att[l];
    o_frag[cta*128 + tid] = acc;
}

// ============================================================
// K3: q_att = Qp @ q_att_W ; f_att = fragp @ f_att_W
// ============================================================
__global__ void __launch_bounds__(256) attproj_kernel(
    const float* __restrict__ qp, const float* __restrict__ qW,
    const float* __restrict__ fW)
{
    extern __shared__ float sm[];
    float* Xs  = sm;          // 64*128
    float* Wsm = sm + 8192;   // 128*64
    int r0 = blockIdx.x * 64;
    const float* src; const float* Wg; float* dst;
    if (r0 < 512) { src = qp + r0*128;               Wg = qW; dst = g_qatt + r0*64; }
    else          { src = g_fragp + (r0 - 512)*128;  Wg = fW; dst = g_fatt + (r0 - 512)*64; }
    int tid = threadIdx.x;
    const float4* s4 = (const float4*)src;
    float4* Xs4 = (float4*)Xs;
#pragma unroll
    for (int it = 0; it < 8; ++it) Xs4[tid + it*256] = s4[tid + it*256];
    const float4* W4 = (const float4*)Wg;
    float4* Wsm4 = (float4*)Wsm;
#pragma unroll
    for (int it = 0; it < 8; ++it) Wsm4[tid + it*256] = W4[tid + it*256];
    __syncthreads();
    int tx = tid & 15, ty = tid >> 4;
    float acc[4][4];
#pragma unroll
    for (int i = 0; i < 4; ++i)
#pragma unroll
        for (int j = 0; j < 4; ++j) acc[i][j] = 0.f;
#pragma unroll 4
    for (int k = 0; k < 128; ++k) {
        float a0 = Xs[(ty*4+0)*128+k], a1 = Xs[(ty*4+1)*128+k];
        float a2 = Xs[(ty*4+2)*128+k], a3 = Xs[(ty*4+3)*128+k];
        float4 wv = Wsm4[k*16 + tx];
        float wb[4] = {wv.x, wv.y, wv.z, wv.w};
#pragma unroll
        for (int j = 0; j < 4; ++j) {
            acc[0][j] += a0*wb[j]; acc[1][j] += a1*wb[j];
            acc[2][j] += a2*wb[j]; acc[3][j] += a3*wb[j];
        }
    }
#pragma unroll
    for (int i = 0; i < 4; ++i) {
        int r = ty*4 + i;
#pragma unroll
        for (int j = 0; j < 4; ++j) dst[r*64 + tx*4 + j] = acc[i][j];
    }
}

// ============================================================
// K4: qf_part[q,v] = max_{l in half} ( f_att[l,v] + sum_d Q[q,d]*s_l[d]*W[d,v] )
// grid 128 CTAs = (b,g) x l-half(32), 256 thr.
// CTA tile: 128q x 64v; thread tile 8q x 4v x 2l; acc packed over q (fma.rn.f32x2).
// Per k per thread: 4 LDS.128 feed 32 FFMA2 -> LDS/FMA balanced at 128 cyc/k/CTA.
// ============================================================
__global__ void __launch_bounds__(256) big_kernel(
    const float* __restrict__ qp, const float* __restrict__ qfW)
{
    extern __shared__ float sm[];
    float* Qt   = sm;              // [128][132] k-major Q (full 128 q)
    float* Wsm  = sm + 16896;      // [128][68]  raw qf_att_W, padded rows
    float* Ws2  = sm + 25600;      // [2][128][68] scaled W for l0,l1
    float* s_s  = sm + 43008;      // [2][128]
    float* fa_s = sm + 43264;      // [2][64]

    int cta = blockIdx.x;
    int bg = cta >> 1;             // b*16+g
    int lh = cta & 1;
    int b  = bg >> 4;
    int tid = threadIdx.x;
    int fragbase = bg * 64;

    // ---- stage Q k-major: Qt[k][q] = Q[b][q][k]
    // mapping: q = idx&127 (lane-consecutive -> conflict-free STS), k4 = idx>>7
    const float* qb = qp + (b * 128) * 128;
#pragma unroll
    for (int it = 0; it < 16; ++it) {
        int idx = tid + it * 256;          // 0..4095
        int q  = idx & 127;
        int k4 = idx >> 7;                 // 0..31
        float4 v = *(const float4*)(qb + q*128 + k4*4);
        Qt[(k4*4+0)*132 + q] = v.x;
        Qt[(k4*4+1)*132 + q] = v.y;
        Qt[(k4*4+2)*132 + q] = v.z;
        Qt[(k4*4+3)*132 + q] = v.w;
    }
    // ---- stage W (padded rows of 68 floats = 17 float4)
    {
        const float4* W4 = (const float4*)qfW;
#pragma unroll
        for (int it = 0; it < 8; ++it) {
            int idx = tid + it * 256;      // 0..2047
            int k = idx >> 4, j = idx & 15;
            ((float4*)Wsm)[k*17 + j] = W4[idx];
        }
    }

    int tx = tid & 15, ty = tid >> 4;      // tx: v-group (v=tx*4), ty: q-group (q=ty*8)
    const float* Qtp = Qt + ty * 8;
    const float* W0p = Ws2 + tx * 4;
    const float* W1p = Ws2 + 128*68 + tx * 4;

    // prep assignment: 128 threads per l, one full k-row each
    int prep_k = tid & 127, prep_p = tid >> 7;
    float* WsRow = Ws2 + (prep_p * 128 + prep_k) * 68;
    const float4* WsmRow = (const float4*)(Wsm + prep_k * 68);

    unsigned long long acc[2][4][4];
    float M[8][4];
#pragma unroll
    for (int i = 0; i < 8; ++i)
#pragma unroll
        for (int j = 0; j < 4; ++j) M[i][j] = -3.4e38f;
#pragma unroll
    for (int p = 0; p < 2; ++p)
#pragma unroll
        for (int i = 0; i < 4; ++i)
#pragma unroll
            for (int j = 0; j < 4; ++j) acc[p][i][j] = 0ULL;

    for (int lp = 0; lp < 16; ++lp) {
        int l0 = lh * 32 + lp * 2;
        __syncthreads();   // covers staging (lp==0) and prev iter's Ws2 reads
        if (tid < 128) s_s[tid] = g_fragp[(fragbase + l0    ) * 128 + tid];
        else           s_s[tid] = g_fragp[(fragbase + l0 + 1) * 128 + (tid - 128)];
        if (tid < 64)       fa_s[tid] = g_fatt[(bg*64 + l0    ) * 64 + tid];
        else if (tid < 128) fa_s[tid] = g_fatt[(bg*64 + l0 + 1) * 64 + (tid - 64)];
        __syncthreads();

        // Ws2[p][k][v] = s_p[k] * W[k][v]
        {
            float sv = s_s[prep_p * 128 + prep_k];
#pragma unroll
            for (int j = 0; j < 16; ++j) {
                float4 wv = WsmRow[j];
                float4 r; r.x = wv.x*sv; r.y = wv.y*sv; r.z = wv.z*sv; r.w = wv.w*sv;
                *(float4*)(WsRow + j * 4) = r;
            }
        }
        __syncthreads();

#pragma unroll 4
        for (int k = 0; k < 128; ++k) {
            ulonglong2 aA = *(const ulonglong2*)(Qtp + k*132);      // q pairs (0,1),(2,3)
            ulonglong2 aB = *(const ulonglong2*)(Qtp + k*132 + 4);  // q pairs (4,5),(6,7)
            float4 w0 = *(const float4*)(W0p + k*68);
            float4 w1 = *(const float4*)(W1p + k*68);
            unsigned long long a[4] = {aA.x, aA.y, aB.x, aB.y};
            unsigned long long b0[4] = {dup_f32(w0.x), dup_f32(w0.y), dup_f32(w0.z), dup_f32(w0.w)};
            unsigned long long b1[4] = {dup_f32(w1.x), dup_f32(w1.y), dup_f32(w1.z), dup_f32(w1.w)};
#pragma unroll
            for (int qp_ = 0; qp_ < 4; ++qp_) {
#pragma unroll
                for (int j = 0; j < 4; ++j) fma2(acc[0][qp_][j], a[qp_], b0[j]);
#pragma unroll
                for (int j = 0; j < 4; ++j) fma2(acc[1][qp_][j], a[qp_], b1[j]);
            }
        }

        // epilogue: add f_att, running max, reset acc
#pragma unroll
        for (int p = 0; p < 2; ++p) {
            float fav[4] = { fa_s[p*64 + tx*4 + 0], fa_s[p*64 + tx*4 + 1],
                             fa_s[p*64 + tx*4 + 2], fa_s[p*64 + tx*4 + 3] };
#pragma unroll
            for (int qp_ = 0; qp_ < 4; ++qp_) {
#pragma unroll
                for (int j = 0; j < 4; ++j) {
                    float lo, hi;
                    unpack2(acc[p][qp_][j], lo, hi);
                    M[2*qp_    ][j] = fmaxf(M[2*qp_    ][j], lo + fav[j]);
                    M[2*qp_ + 1][j] = fmaxf(M[2*qp_ + 1][j], hi + fav[j]);
                    acc[p][qp_][j] = 0ULL;
                }
            }
        }
    }

    // store partial max (q_att added in K5)
    float* outp = (lh == 0) ? g_qf : g_qf2;
#pragma unroll
    for (int i = 0; i < 8; ++i) {
        int q = ty * 8 + i;
        float4 st; st.x = M[i][0]; st.y = M[i][1]; st.z = M[i][2]; st.w = M[i][3];
        *(float4*)(outp + (bg*128 + q) * 64 + tx * 4) = st;
    }
}

// ============================================================
// K5: combine partial maxes + q_att; gate/val softmax over LQ + query_code
// ============================================================
__global__ void __launch_bounds__(128) final_kernel(
    const float* __restrict__ qp, const float* __restrict__ qmask,
    const float* __restrict__ gate_w, const float* __restrict__ val_w,
    float* __restrict__ o_gate, float* __restrict__ o_qc)
{
    __shared__ float gw[64], vw[64], red[128], norm[128];
    int bg = blockIdx.x;
    int b = bg >> 4;
    int tid = threadIdx.x;
    if (tid < 64) { gw[tid] = gate_w[tid]; vw[tid] = val_w[tid]; }
    __syncthreads();
    const float* r1 = g_qf  + (bg*128 + tid) * 64;
    const float* r2 = g_qf2 + (bg*128 + tid) * 64;
    const float* qa = g_qatt + (b*128 + tid) * 64;
    float dg = 0.f, dv = 0.f;
#pragma unroll 4
    for (int v = 0; v < 64; ++v) {
        float x = fmaxf(r1[v], r2[v]) + qa[v];
        dg += x * gw[v]; dv += x * vw[v];
    }
    float qm = qmask[b*128 + tid];
    o_gate[bg*128 + tid] = qm / (1.f + expf(-dg));
    float e2 = expf(dv) * qm;
    red[tid] = e2;
    __syncthreads();
    for (int s = 64; s > 0; s >>= 1) {
        if (tid < s) red[tid] += red[tid + s];
        __syncthreads();
    }
    norm[tid] = e2 / (red[0] + 1e-7f);
    __syncthreads();
    const float* qpb = qp + b * 128 * 128;
    float acc = 0.f;
#pragma unroll 4
    for (int q = 0; q < 128; ++q) acc += qpb[q*128 + tid] * norm[q];
    o_qc[bg*128 + tid] = acc;
}

// ============================================================
extern "C" void kernel_launch(void* const* d_in, const int* in_sizes, int n_in,
                              void* d_out, int out_size)
{
    (void)in_sizes; (void)n_in;
    const float* query    = (const float*)d_in[0];
    const float* fragment = (const float*)d_in[1];
    const float* qmask    = (const float*)d_in[2];
    const float* fmask    = (const float*)d_in[3];
    const float* proj_W   = (const float*)d_in[4];
    const float* proj_b   = (const float*)d_in[5];
    const float* selfW    = (const float*)d_in[6];
    const float* qattW    = (const float*)d_in[7];
    const float* fattW    = (const float*)d_in[8];
    const float* qfW      = (const float*)d_in[9];
    const float* gatew    = (const float*)d_in[10];
    const float* valw     = (const float*)d_in[11];
    float* out = (float*)d_out;

    float *o_frag, *o_qc, *o_fsa, *o_gate, *o_q;
    if (out_size >= OUT_TOTAL) {
        o_frag = out + OC_FRAG; o_qc = out + OC_QC; o_fsa = out + OC_FSA;
        o_gate = out + OC_GATE; o_q = out + OC_Q;
    } else {
        float* dp = nullptr;
        cudaGetSymbolAddress((void**)&dp, g_dump);
        float* qpd = nullptr;
        cudaGetSymbolAddress((void**)&qpd, g_qp);
        o_frag = dp + OC_FRAG; o_qc = dp + OC_QC; o_fsa = dp + OC_FSA;
        o_gate = dp + OC_GATE; o_q = qpd;
    }

    cudaFuncSetAttribute(proj_kernel,    cudaFuncAttributeMaxDynamicSharedMemorySize, 98304);
    cudaFuncSetAttribute(attproj_kernel, cudaFuncAttributeMaxDynamicSharedMemorySize, 65536);
    cudaFuncSetAttribute(big_kernel,     cudaFuncAttributeMaxDynamicSharedMemorySize, 173568);

    proj_kernel   <<<72, 256, 98304>>>(query, fragment, proj_W, proj_b, o_q);
    selfatt_kernel<<<64, 128>>>(selfW, fmask, o_fsa, o_frag);
    attproj_kernel<<<72, 256, 65536>>>(o_q, qattW, fattW);
    big_kernel    <<<128, 256, 173568>>>(o_q, qfW);
    final_kernel  <<<64, 128>>>(o_q, qmask, gatew, valw, o_gate, o_qc);
}